// round 5
// baseline (speedup 1.0000x reference)
#include <cuda_runtime.h>

#define NB   64
#define SEQ  512
#define DIM  64
#define BIGF 1e30f
#define LOG2E 1.44269504088896340736f
#define LN2   0.69314718055994530942f

typedef unsigned long long u64;

// Scratch (static device globals — allocation-free per harness rules)
__device__ float g_D[(size_t)NB * SEQ * SEQ];   // 64 MiB, row-major per batch, pre-scaled by log2e
__device__ float g_x2[NB * SEQ];
__device__ float g_y2[NB * SEQ];

// ---------------------------------------------------------------------------
// f32x2 packed helpers (sm_103a FFMA2 path — PTX only, ptxas won't auto-fuse)
// ---------------------------------------------------------------------------
__device__ __forceinline__ u64 ffma2(u64 a, u64 b, u64 c) {
    u64 d;
    asm("fma.rn.f32x2 %0, %1, %2, %3;" : "=l"(d) : "l"(a), "l"(b), "l"(c));
    return d;
}
__device__ __forceinline__ u64 pack2(float lo, float hi) {
    u64 d;
    asm("mov.b64 %0, {%1, %2};" : "=l"(d) : "f"(lo), "f"(hi));
    return d;
}
__device__ __forceinline__ float2 unpack2(u64 v) {
    float2 r;
    asm("mov.b64 {%0, %1}, %2;" : "=f"(r.x), "=f"(r.y) : "l"(v));
    return r;
}
__device__ __forceinline__ float ex2(float x) {
    float r; asm("ex2.approx.ftz.f32 %0, %1;" : "=f"(r) : "f"(x)); return r;
}
__device__ __forceinline__ float lg2(float x) {
    float r; asm("lg2.approx.ftz.f32 %0, %1;" : "=f"(r) : "f"(x)); return r;
}

// ---------------------------------------------------------------------------
// Kernel 0: row norms. 8 threads per row, 32 rows per 256-thread block.
// ---------------------------------------------------------------------------
__global__ __launch_bounds__(256) void rownorm_kernel(const float* __restrict__ A, int which) {
    int row = blockIdx.x * 32 + (threadIdx.x >> 3);
    int l = threadIdx.x & 7;
    const float4* a = (const float4*)(A + (size_t)row * DIM);
    float4 v1 = __ldg(&a[l * 2]);
    float4 v2 = __ldg(&a[l * 2 + 1]);
    float s = v1.x*v1.x + v1.y*v1.y + v1.z*v1.z + v1.w*v1.w
            + v2.x*v2.x + v2.y*v2.y + v2.z*v2.z + v2.w*v2.w;
    s += __shfl_down_sync(0xffffffffu, s, 4);
    s += __shfl_down_sync(0xffffffffu, s, 2);
    s += __shfl_down_sync(0xffffffffu, s, 1);
    if (l == 0) {
        float* out = which ? g_y2 : g_x2;
        out[row] = s;
    }
}

// ---------------------------------------------------------------------------
// Kernel 1: pairwise squared distances with packed f32x2 FFMA2.
// D[b][i][j] = log2e * (x2[i] + y2[j] - 2 * dot(x_i, y_j))   (pre-scaled!)
// ---------------------------------------------------------------------------
#define BM 128
#define BN 128
#define BK 16
#define STRX 34
#define STRY 34

__global__ __launch_bounds__(256, 2) void pairdist_kernel(const float* __restrict__ X,
                                                          const float* __restrict__ Y) {
    __shared__ float Xs2[BM * STRX];
    __shared__ float Ys2[64 * STRY];

    int b  = blockIdx.z;
    int i0 = blockIdx.y * BM;
    int j0 = blockIdx.x * BN;
    const float* Xb = X + (size_t)b * SEQ * DIM + (size_t)i0 * DIM;
    const float* Yb = Y + (size_t)b * SEQ * DIM + (size_t)j0 * DIM;

    int tid = threadIdx.x;
    int tx = tid & 15;
    int ty = tid >> 4;

    u64 acc2[8][4];
#pragma unroll
    for (int r = 0; r < 8; r++)
#pragma unroll
        for (int c2 = 0; c2 < 4; c2++) acc2[r][c2] = 0ull;

    for (int k0 = 0; k0 < DIM; k0 += BK) {
        __syncthreads();
#pragma unroll
        for (int q = 0; q < 2; q++) {
            int idx = tid + q * 256;
            int r  = idx >> 2;
            int c4 = idx & 3;
            float4 xv = __ldg((const float4*)(Xb + (size_t)r * DIM + k0 + c4 * 4));
            float4 yv = __ldg((const float4*)(Yb + (size_t)r * DIM + k0 + c4 * 4));
            u64* xs = (u64*)&Xs2[r * STRX + c4 * 8];
            xs[0] = pack2(xv.x, xv.x);
            xs[1] = pack2(xv.y, xv.y);
            xs[2] = pack2(xv.z, xv.z);
            xs[3] = pack2(xv.w, xv.w);
            int pr   = (r & 15) + 16 * (r >> 5);
            int slot = (r >> 4) & 1;
            float* ys = &Ys2[pr * STRY + c4 * 8 + slot];
            ys[0] = yv.x; ys[2] = yv.y; ys[4] = yv.z; ys[6] = yv.w;
        }
        __syncthreads();

#pragma unroll
        for (int k = 0; k < BK; k++) {
            u64 bb[4];
#pragma unroll
            for (int c2 = 0; c2 < 4; c2++)
                bb[c2] = *(const u64*)&Ys2[(tx + 16 * c2) * STRY + k * 2];
#pragma unroll
            for (int r = 0; r < 8; r++) {
                u64 aa = *(const u64*)&Xs2[(ty + 16 * r) * STRX + k * 2];
#pragma unroll
                for (int c2 = 0; c2 < 4; c2++)
                    acc2[r][c2] = ffma2(aa, bb[c2], acc2[r][c2]);
            }
        }
    }

    float yn[8];
#pragma unroll
    for (int c = 0; c < 8; c++) yn[c] = g_y2[b * SEQ + j0 + tx + 16 * c];
    float* Db = g_D + (size_t)b * SEQ * SEQ;
#pragma unroll
    for (int r = 0; r < 8; r++) {
        int i = i0 + ty + 16 * r;
        float xn = g_x2[b * SEQ + i];
#pragma unroll
        for (int c2 = 0; c2 < 4; c2++) {
            float2 d2 = unpack2(acc2[r][c2]);
            int jA = j0 + tx + 16 * (2 * c2);
            int jB = j0 + tx + 16 * (2 * c2 + 1);
            Db[(size_t)i * SEQ + jA] = LOG2E * (xn + yn[2 * c2]     - 2.0f * d2.x);
            Db[(size_t)i * SEQ + jB] = LOG2E * (xn + yn[2 * c2 + 1] - 2.0f * d2.y);
        }
    }
}

// ---------------------------------------------------------------------------
// Kernel 2: soft-DTW wavefront. 128 threads (4 warps, ONE PER SMSP — spin
// polls cannot starve producers across SMSPs). Thread owns 4 consecutive rows
// base..base+3 (base = 4*tid). Per diagonal p the 4 cells are independent
// (all deps come from p-1 / p-2):
//   l = own val (reg), u = row-above val from p-1 (reg for r>0, shfl/mailbox
//   for r==0), a = row-above val from p-2 (= previous beat's u, reg).
// 3 warp-boundary mailboxes: lane 31 publishes its bottom-row val (volatile
// 32-bit STS into canary-initialized slot); next warp broadcast-polls.
// Log2-domain softmin (D pre-scaled by log2e):
//   lo=min(u,l); hi=max(u,l); mn=min(a,lo); m1=max(a,lo)
//   val = d + mn - lg2(1 + 2^(mn-m1) + 2^(mn-hi))      (2 EX2 + 1 LG2)
// ---------------------------------------------------------------------------
#define CANARY 0xFFC00001u
#define RPT 4
#define TPB (SEQ / RPT)   // 128

__global__ __launch_bounds__(TPB) void softdtw_kernel(float* __restrict__ out) {
    int b    = blockIdx.x;
    int tid  = threadIdx.x;
    int w    = tid >> 5;
    int lane = tid & 31;
    int base = tid * RPT;

    __shared__ unsigned int bnd[3 * SEQ];   // 6 KB: boundaries after warps 0,1,2
    for (int k = tid; k < 3 * SEQ; k += TPB) bnd[k] = CANARY;
    __syncthreads();

    const float* Db = g_D + (size_t)b * SEQ * SEQ;
    const float4* row4[RPT];
    float4 bufA[RPT], bufB[RPT];
    int nxt[RPT];
    float v1[RPT], areg[RPT];
#pragma unroll
    for (int r = 0; r < RPT; r++) {
        row4[r] = (const float4*)(Db + (size_t)(base + r) * SEQ);
        bufA[r] = __ldg(row4[r]);
        bufB[r] = __ldg(row4[r] + 1);
        nxt[r]  = 2;
        v1[r]   = BIGF;
        areg[r] = BIGF;
    }
    if (tid == 0) areg[0] = 0.0f;   // cell (0,0): diagonal predecessor = 0

    volatile unsigned int* rslot = &bnd[(w > 0 ? (w - 1) : 0) * SEQ];
    volatile unsigned int* wslot = &bnd[(w < 3 ? w : 0) * SEQ];

    int p0   = w * (TPB / 4) * RPT;        // = w * 128
    int pend = p0 + 128 + SEQ - 1;         // 639 beats per warp

    for (int p = p0; p < pend; ++p) {
        int idx = p - p0;                               // lane 0 top-row j (warp-uniform)
        float sh = __shfl_up_sync(0xffffffffu, v1[RPT - 1], 1);
        if (w > 0 && idx < SEQ) {
            unsigned int vv = rslot[idx];               // broadcast poll, one slot
            while (vv == CANARY) vv = rslot[idx];
            if (lane == 0) sh = __uint_as_float(vv);
        }
        if (w == 0 && lane == 0) sh = BIGF;             // global row 0: no row above

        // rows descending so v1[r-1] still holds the beat-(p-1) value
#pragma unroll
        for (int r = RPT - 1; r >= 0; --r) {
            int j = idx - 4 * lane - r;
            if (j >= 0 && j < SEQ) {
                int m = j & 3;
                float d = (m == 0) ? bufA[r].x : (m == 1) ? bufA[r].y
                        : (m == 2) ? bufA[r].z : bufA[r].w;
                if (m == 3) {
                    bufA[r] = bufB[r];
                    if (nxt[r] < SEQ / 4) bufB[r] = __ldg(row4[r] + nxt[r]);
                    nxt[r]++;
                }
                float u  = (r == 0) ? sh : v1[r - 1];
                float a  = areg[r];
                float l  = v1[r];
                float lo = fminf(u, l), hi = fmaxf(u, l);
                float mn = fminf(a, lo), m1 = fmaxf(a, lo);
                float s  = 1.0f + ex2(mn - m1) + ex2(mn - hi);
                float nv = d + (mn - lg2(s));
                v1[r]   = nv;
                areg[r] = u;
                if (r == RPT - 1 && lane == 31) {
                    if (w < 3) wslot[j] = __float_as_uint(nv);
                    else if (j == SEQ - 1) out[b] = nv * LN2;
                }
            }
        }
    }
}

// ---------------------------------------------------------------------------
extern "C" void kernel_launch(void* const* d_in, const int* in_sizes, int n_in,
                              void* d_out, int out_size) {
    const float* x = (const float*)d_in[0];
    const float* y = (const float*)d_in[1];
    float* out = (float*)d_out;

    rownorm_kernel<<<NB * SEQ / 32, 256>>>(x, 0);
    rownorm_kernel<<<NB * SEQ / 32, 256>>>(y, 1);

    dim3 g(SEQ / BN, SEQ / BM, NB);
    pairdist_kernel<<<g, 256>>>(x, y);

    softdtw_kernel<<<NB, TPB>>>(out);
}

// round 6
// speedup vs baseline: 1.3844x; 1.3844x over previous
#include <cuda_runtime.h>

#define NB   64
#define SEQ  512
#define DIM  64
#define BIGF 1e30f
#define LOG2E 1.44269504088896340736f
#define LN2   0.69314718055994530942f
#define CANARY 0xFFC00001u

typedef unsigned long long u64;

// Scratch (static device globals — allocation-free per harness rules)
__device__ float g_D[(size_t)NB * SEQ * SEQ];        // 64 MiB, row-major per batch, pre-scaled by log2e
__device__ float g_x2[NB * SEQ];
__device__ float g_y2[NB * SEQ];
__device__ unsigned int g_bnd[NB][SEQ];              // row-255 boundary mailbox (canary protocol)

// ---------------------------------------------------------------------------
// f32x2 packed helpers (sm_103a FFMA2 path — PTX only, ptxas won't auto-fuse)
// ---------------------------------------------------------------------------
__device__ __forceinline__ u64 ffma2(u64 a, u64 b, u64 c) {
    u64 d;
    asm("fma.rn.f32x2 %0, %1, %2, %3;" : "=l"(d) : "l"(a), "l"(b), "l"(c));
    return d;
}
__device__ __forceinline__ u64 pack2(float lo, float hi) {
    u64 d;
    asm("mov.b64 %0, {%1, %2};" : "=l"(d) : "f"(lo), "f"(hi));
    return d;
}
__device__ __forceinline__ float2 unpack2(u64 v) {
    float2 r;
    asm("mov.b64 {%0, %1}, %2;" : "=f"(r.x), "=f"(r.y) : "l"(v));
    return r;
}
__device__ __forceinline__ float ex2(float x) {
    float r; asm("ex2.approx.ftz.f32 %0, %1;" : "=f"(r) : "f"(x)); return r;
}
__device__ __forceinline__ float lg2(float x) {
    float r; asm("lg2.approx.ftz.f32 %0, %1;" : "=f"(r) : "f"(x)); return r;
}

// ---------------------------------------------------------------------------
// Kernel: reset global boundary mailbox to canaries (every replay).
// ---------------------------------------------------------------------------
__global__ void bndinit_kernel() {
    g_bnd[blockIdx.x][threadIdx.x] = CANARY;
}

// ---------------------------------------------------------------------------
// Kernel 0: row norms. 8 threads per row, 32 rows per 256-thread block.
// ---------------------------------------------------------------------------
__global__ __launch_bounds__(256) void rownorm_kernel(const float* __restrict__ A, int which) {
    int row = blockIdx.x * 32 + (threadIdx.x >> 3);
    int l = threadIdx.x & 7;
    const float4* a = (const float4*)(A + (size_t)row * DIM);
    float4 v1 = __ldg(&a[l * 2]);
    float4 v2 = __ldg(&a[l * 2 + 1]);
    float s = v1.x*v1.x + v1.y*v1.y + v1.z*v1.z + v1.w*v1.w
            + v2.x*v2.x + v2.y*v2.y + v2.z*v2.z + v2.w*v2.w;
    s += __shfl_down_sync(0xffffffffu, s, 4);
    s += __shfl_down_sync(0xffffffffu, s, 2);
    s += __shfl_down_sync(0xffffffffu, s, 1);
    if (l == 0) {
        float* out = which ? g_y2 : g_x2;
        out[row] = s;
    }
}

// ---------------------------------------------------------------------------
// Kernel 1: pairwise squared distances with packed f32x2 FFMA2.
// D[b][i][j] = log2e * (x2[i] + y2[j] - 2 * dot(x_i, y_j))   (pre-scaled!)
// ---------------------------------------------------------------------------
#define BM 128
#define BN 128
#define BK 16
#define STRX 34
#define STRY 34

__global__ __launch_bounds__(256, 2) void pairdist_kernel(const float* __restrict__ X,
                                                          const float* __restrict__ Y) {
    __shared__ float Xs2[BM * STRX];
    __shared__ float Ys2[64 * STRY];

    int b  = blockIdx.z;
    int i0 = blockIdx.y * BM;
    int j0 = blockIdx.x * BN;
    const float* Xb = X + (size_t)b * SEQ * DIM + (size_t)i0 * DIM;
    const float* Yb = Y + (size_t)b * SEQ * DIM + (size_t)j0 * DIM;

    int tid = threadIdx.x;
    int tx = tid & 15;
    int ty = tid >> 4;

    u64 acc2[8][4];
#pragma unroll
    for (int r = 0; r < 8; r++)
#pragma unroll
        for (int c2 = 0; c2 < 4; c2++) acc2[r][c2] = 0ull;

    for (int k0 = 0; k0 < DIM; k0 += BK) {
        __syncthreads();
#pragma unroll
        for (int q = 0; q < 2; q++) {
            int idx = tid + q * 256;
            int r  = idx >> 2;
            int c4 = idx & 3;
            float4 xv = __ldg((const float4*)(Xb + (size_t)r * DIM + k0 + c4 * 4));
            float4 yv = __ldg((const float4*)(Yb + (size_t)r * DIM + k0 + c4 * 4));
            u64* xs = (u64*)&Xs2[r * STRX + c4 * 8];
            xs[0] = pack2(xv.x, xv.x);
            xs[1] = pack2(xv.y, xv.y);
            xs[2] = pack2(xv.z, xv.z);
            xs[3] = pack2(xv.w, xv.w);
            int pr   = (r & 15) + 16 * (r >> 5);
            int slot = (r >> 4) & 1;
            float* ys = &Ys2[pr * STRY + c4 * 8 + slot];
            ys[0] = yv.x; ys[2] = yv.y; ys[4] = yv.z; ys[6] = yv.w;
        }
        __syncthreads();

#pragma unroll
        for (int k = 0; k < BK; k++) {
            u64 bb[4];
#pragma unroll
            for (int c2 = 0; c2 < 4; c2++)
                bb[c2] = *(const u64*)&Ys2[(tx + 16 * c2) * STRY + k * 2];
#pragma unroll
            for (int r = 0; r < 8; r++) {
                u64 aa = *(const u64*)&Xs2[(ty + 16 * r) * STRX + k * 2];
#pragma unroll
                for (int c2 = 0; c2 < 4; c2++)
                    acc2[r][c2] = ffma2(aa, bb[c2], acc2[r][c2]);
            }
        }
    }

    float yn[8];
#pragma unroll
    for (int c = 0; c < 8; c++) yn[c] = g_y2[b * SEQ + j0 + tx + 16 * c];
    float* Db = g_D + (size_t)b * SEQ * SEQ;
#pragma unroll
    for (int r = 0; r < 8; r++) {
        int i = i0 + ty + 16 * r;
        float xn = g_x2[b * SEQ + i];
#pragma unroll
        for (int c2 = 0; c2 < 4; c2++) {
            float2 d2 = unpack2(acc2[r][c2]);
            int jA = j0 + tx + 16 * (2 * c2);
            int jB = j0 + tx + 16 * (2 * c2 + 1);
            Db[(size_t)i * SEQ + jA] = LOG2E * (xn + yn[2 * c2]     - 2.0f * d2.x);
            Db[(size_t)i * SEQ + jB] = LOG2E * (xn + yn[2 * c2 + 1] - 2.0f * d2.y);
        }
    }
}

// ---------------------------------------------------------------------------
// Kernel 2: soft-DTW wavefront. 2 CTAs per batch (rows [0,256) / [256,512)).
// Per CTA: 8 DP warps (1 row/thread, 1 cell/beat) + 1 copier warp.
//   u = shfl_up(val) (lane>0) or mailbox (lane 0); a = previous beat's u (reg);
//   l = own val (reg). Lane 31 publishes its val: smem mailbox (w<7), global
//   canary mailbox (half 0, w==7), or the final output (half 1, w==7, j=511).
// Copier warp (half 1 only) stages g_bnd -> smem slot 7 off the critical path.
// Poll: one cheap retry, then __nanosleep loop (no arbiter monopolization).
// Fast path: softmin correction lg2(1+2^(mn-m1)+2^(mn-hi)) < 2^-22 when
// m1-mn >= 24 (log2 domain) -> warp-voted skip of all 3 MUFUs.
// ---------------------------------------------------------------------------
#define WARPS_DP 8
#define TPB_DP (WARPS_DP * 32 + 32)   // 288: 8 DP warps + 1 copier warp

__global__ __launch_bounds__(TPB_DP) void softdtw_kernel(float* __restrict__ out) {
    int halfId = blockIdx.x;          // 0: rows 0..255, 1: rows 256..511
    int b      = blockIdx.y;
    int tid    = threadIdx.x;
    int w      = tid >> 5;
    int lane   = tid & 31;

    __shared__ unsigned int bnd[WARPS_DP][SEQ];   // 16 KB mailbox slots
    for (int k = tid; k < WARPS_DP * SEQ; k += TPB_DP)
        ((unsigned int*)bnd)[k] = CANARY;
    __syncthreads();

    if (w == WARPS_DP) {
        // copier warp: stage global boundary (row 255) into smem slot 7
        if (halfId == 1) {
            volatile unsigned int* src = &g_bnd[b][0];
            for (int c = lane; c < SEQ; c += 32) {
                unsigned int v = src[c];
                while (v == CANARY) { __nanosleep(64); v = src[c]; }
                ((volatile unsigned int*)bnd[7])[c] = v;
            }
        }
        return;
    }

    int i = halfId * 256 + w * 32 + lane;
    const float4* row4 = (const float4*)(g_D + (size_t)b * SEQ * SEQ + (size_t)i * SEQ);
    float4 bufA = __ldg(row4);
    float4 bufB = __ldg(row4 + 1);
    float4 bufC = __ldg(row4 + 2);
    int nxt = 3;

    float val  = BIGF;
    float areg = (i == 0) ? 0.0f : BIGF;   // (0,0): diagonal predecessor = 0

    bool hasSrc = (w > 0) || (halfId == 1);
    volatile unsigned int* rslot = (w > 0) ? bnd[w - 1] : bnd[7];
    volatile unsigned int* wslot = bnd[(w < 7) ? w : 0];
    volatile unsigned int* gdst  = &g_bnd[b][0];
    bool isGlobalPub = (halfId == 0) && (w == 7);
    bool isLast      = (halfId == 1) && (w == 7);

    for (int idx = 0; idx < SEQ + 31; ++idx) {
        int j = idx - lane;
        float sh = __shfl_up_sync(0xffffffffu, val, 1);
        float u = sh;
        if (hasSrc) {
            if (idx < SEQ) {
                unsigned int v = rslot[idx];           // broadcast LDS
                if (v == CANARY) {
                    v = rslot[idx];                    // one cheap retry
                    while (v == CANARY) { __nanosleep(32); v = rslot[idx]; }
                }
                if (lane == 0) u = __uint_as_float(v);
            }
        } else if (lane == 0) {
            u = BIGF;                                  // global row 0: nothing above
        }

        float a = areg, l = val;
        float lo = fminf(u, l), hi = fmaxf(u, l);
        float mn = fminf(a, lo), m1 = fmaxf(a, lo);

        bool act = (j >= 0) && (j < SEQ);
        int m = j & 3;
        float d = (m == 0) ? bufA.x : (m == 1) ? bufA.y : (m == 2) ? bufA.z : bufA.w;

        float corr = 0.0f;
        bool need = act && (m1 - mn < 24.0f);
        if (__any_sync(0xffffffffu, need)) {
            float s = 1.0f + ex2(mn - m1) + ex2(mn - hi);
            corr = lg2(s);
        }
        float nv = d + mn - corr;
        areg = u;

        if (act) {
            val = nv;
            if (m == 3) {
                bufA = bufB; bufB = bufC;
                if (nxt < SEQ / 4) bufC = __ldg(row4 + nxt);
                nxt++;
            }
            if (lane == 31) {
                unsigned int bits = __float_as_uint(nv);
                if (isGlobalPub)       gdst[j]  = bits;
                else if (!isLast)      wslot[j] = bits;
                else if (j == SEQ - 1) out[b]   = nv * LN2;
            }
        }
    }
}

// ---------------------------------------------------------------------------
extern "C" void kernel_launch(void* const* d_in, const int* in_sizes, int n_in,
                              void* d_out, int out_size) {
    const float* x = (const float*)d_in[0];
    const float* y = (const float*)d_in[1];
    float* out = (float*)d_out;

    bndinit_kernel<<<NB, SEQ>>>();

    rownorm_kernel<<<NB * SEQ / 32, 256>>>(x, 0);
    rownorm_kernel<<<NB * SEQ / 32, 256>>>(y, 1);

    dim3 g(SEQ / BN, SEQ / BM, NB);
    pairdist_kernel<<<g, 256>>>(x, y);

    dim3 gd(2, NB);
    softdtw_kernel<<<gd, TPB_DP>>>(out);
}